// round 4
// baseline (speedup 1.0000x reference)
#include <cuda_runtime.h>
#include <stdint.h>

// Fixed-shape problem constants
#define HH 352
#define WW 1216
#define PP 65536
#define CC 64
#define BB 2
#define HW (HH * WW)            // 428032 (divisible by 4)
#define NPIX (BB * HW)          // 856064
#define MAXC 8                  // per-pixel candidate capacity (= reference K)

// Scratch (__device__ globals: allocation-free)
__device__ int    d_count[NPIX];
__device__ uint2  d_cand[NPIX * MAXC];          // {pid, bitcast(weight)}
__device__ float  d_featsT[BB * PP * CC];       // src transposed to [B*P, C]

#define T_TILES (PP / 32 * (CC / 32) * BB)      // 8192 transpose tiles
#define Z_BLOCKS (NPIX / 4 / 256)               // 836 zero blocks (exact)

// ------------------------------------------------- transpose + zero counts (fused)
__global__ void __launch_bounds__(256)
prep_kernel(const float* __restrict__ src) {
    int bid = blockIdx.x;
    int tid = threadIdx.x;

    if (bid < T_TILES) {
        // src [B, C, P] -> d_featsT [B*P, C], 32x32 smem tile
        __shared__ float tile[32][33];
        int pb   = bid & (PP / 32 - 1);
        int rest = bid >> 11;
        int cb   = rest & 1;
        int b    = rest >> 1;
        int tx = tid & 31, ty = tid >> 5;
        int pbase = pb * 32, cbase = cb * 32;
        const float* sb = src + (size_t)b * CC * PP;
        #pragma unroll
        for (int j = 0; j < 4; j++) {
            int c = cbase + ty + j * 8;
            tile[ty + j * 8][tx] = sb[(size_t)c * PP + pbase + tx];
        }
        __syncthreads();
        float* ob = d_featsT + ((size_t)b * PP) * CC;
        #pragma unroll
        for (int j = 0; j < 4; j++) {
            int p = pbase + ty + j * 8;
            ob[(size_t)p * CC + cbase + tx] = tile[tx][ty + j * 8];
        }
    } else {
        int z = (bid - T_TILES) * 256 + tid;    // 0 .. NPIX/4-1
        ((int4*)d_count)[z] = make_int4(0, 0, 0, 0);
    }
}

// ------------------------------------------------- build candidate lists
// r = 3/1216 NDC. Row pitch 2/352 > 2r -> only row i0 qualifies.
// Col pitch 2/1216, 2r spans <=3 centers -> only j0-1..j0+1.
__global__ void __launch_bounds__(256)
build_kernel(const float* __restrict__ pts) {
    int t = blockIdx.x * blockDim.x + threadIdx.x;
    if (t >= BB * PP) return;
    int b = t >> 16;

    float x = pts[3 * t + 0];
    float y = pts[3 * t + 1];
    float z = pts[3 * t + 2];

    const float r2     = (3.0f / 1216.0f) * (3.0f / 1216.0f);
    const float inv_r2 = 1216.0f * 1216.0f / 9.0f;

    int i0 = (int)floorf((y + 1.0f) * 0.5f * (float)HH);
    int j0 = (int)floorf((x + 1.0f) * 0.5f * (float)WW);

    if (!(z > 0.0f) || i0 < 0 || i0 >= HH) return;

    float yc  = ((float)i0 + 0.5f) * (2.0f / (float)HH) - 1.0f;
    float fy2 = (y - yc) * (y - yc);

    #pragma unroll
    for (int dxi = -1; dxi <= 1; dxi++) {
        int jj = j0 + dxi;
        if (jj < 0 || jj >= WW) continue;
        float xc = ((float)jj + 0.5f) * (2.0f / (float)WW) - 1.0f;
        float fx = x - xc;
        float d2 = fx * fx + fy2;
        if (d2 < r2) {
            float alpha = 1.0f - sqrtf(fmaxf(d2 * inv_r2, 0.001f));
            int pix = (b * HH + i0) * WW + jj;
            int idx = atomicAdd(&d_count[pix], 1);
            if (idx < MAXC)
                d_cand[pix * MAXC + idx] = make_uint2((unsigned)t, __float_as_uint(alpha));
        }
    }
}

// ------------------------------------------------- gather
// Thread = 4 consecutive pixels x 8 channels. float4 (STG.128) output stores.
__device__ __forceinline__ float fcomp(const float4& v, int k) {
    return k == 0 ? v.x : (k == 1 ? v.y : (k == 2 ? v.z : v.w));
}

__global__ void __launch_bounds__(256)
gather_kernel(float* __restrict__ out) {
    int q = blockIdx.x * 256 + threadIdx.x;     // quad index 0..NPIX/4-1
    int g = blockIdx.y;                          // channel group 0..7
    int pix0 = q * 4;

    int4 cnt = ((const int4*)d_count)[q];

    float4 acc[4][2];
    #pragma unroll
    for (int pl = 0; pl < 4; pl++) {
        acc[pl][0] = make_float4(0.f, 0.f, 0.f, 0.f);
        acc[pl][1] = make_float4(0.f, 0.f, 0.f, 0.f);
    }

    int ns[4] = { cnt.x, cnt.y, cnt.z, cnt.w };
    #pragma unroll
    for (int pl = 0; pl < 4; pl++) {
        int n = ns[pl] < MAXC ? ns[pl] : MAXC;
        for (int i = 0; i < n; i++) {
            uint2 e = d_cand[(pix0 + pl) * MAXC + i];
            float w = __uint_as_float(e.y);
            const float4* fp = (const float4*)(d_featsT + (size_t)e.x * CC + g * 8);
            float4 fa = fp[0];
            float4 fb = fp[1];
            acc[pl][0].x += w * fa.x; acc[pl][0].y += w * fa.y;
            acc[pl][0].z += w * fa.z; acc[pl][0].w += w * fa.w;
            acc[pl][1].x += w * fb.x; acc[pl][1].y += w * fb.y;
            acc[pl][1].z += w * fb.z; acc[pl][1].w += w * fb.w;
        }
    }

    int b   = pix0 / HW;
    int loc = pix0 - b * HW;
    float* base = out + (size_t)b * CC * HW + (size_t)(g * 8) * HW + loc;

    #pragma unroll
    for (int c = 0; c < 8; c++) {
        int j = c >> 2, k = c & 3;
        float4 v = make_float4(fcomp(acc[0][j], k), fcomp(acc[1][j], k),
                               fcomp(acc[2][j], k), fcomp(acc[3][j], k));
        *((float4*)(base + (size_t)c * HW)) = v;
    }
}

extern "C" void kernel_launch(void* const* d_in, const int* in_sizes, int n_in,
                              void* d_out, int out_size) {
    const float* pts = (const float*)d_in[0];   // [B, P, 3]
    const float* src = (const float*)d_in[1];   // [B, C, P]
    float* out = (float*)d_out;                 // [B, C, H, W]

    prep_kernel<<<T_TILES + Z_BLOCKS, 256>>>(src);
    build_kernel<<<(BB * PP) / 256, 256>>>(pts);

    dim3 ggrid(NPIX / 4 / 256, 8);              // (836, 8)
    gather_kernel<<<ggrid, 256>>>(out);
}

// round 5
// speedup vs baseline: 1.3103x; 1.3103x over previous
#include <cuda_runtime.h>
#include <stdint.h>

// Fixed-shape problem constants
#define HH 352
#define WW 1216
#define PP 65536
#define CC 64
#define BB 2
#define HW (HH * WW)            // 428032
#define NPIX (BB * HW)          // 856064
#define MAXC 8                  // per-pixel candidate capacity (= reference K)

// Scratch (__device__ globals: allocation-free)
__device__ int    d_count[NPIX];
__device__ uint2  d_cand[NPIX * MAXC];          // {pid, bitcast(weight)}
__device__ float  d_featsT[BB * PP * CC];       // src transposed to [B*P, C]

#define T_TILES (PP / 32 * (CC / 32) * BB)      // 8192 transpose tiles
#define Z_BLOCKS (NPIX / 4 / 256)               // 836 zero blocks (exact)

// ------------------------------------------------- transpose + zero counts (fused)
__global__ void __launch_bounds__(256)
prep_kernel(const float* __restrict__ src) {
    int bid = blockIdx.x;
    int tid = threadIdx.x;

    if (bid < T_TILES) {
        // src [B, C, P] -> d_featsT [B*P, C], 32x32 smem tile
        __shared__ float tile[32][33];
        int pb   = bid & (PP / 32 - 1);
        int rest = bid >> 11;
        int cb   = rest & 1;
        int b    = rest >> 1;
        int tx = tid & 31, ty = tid >> 5;
        int pbase = pb * 32, cbase = cb * 32;
        const float* sb = src + (size_t)b * CC * PP;
        #pragma unroll
        for (int j = 0; j < 4; j++) {
            int c = cbase + ty + j * 8;
            tile[ty + j * 8][tx] = sb[(size_t)c * PP + pbase + tx];
        }
        __syncthreads();
        float* ob = d_featsT + ((size_t)b * PP) * CC;
        #pragma unroll
        for (int j = 0; j < 4; j++) {
            int p = pbase + ty + j * 8;
            ob[(size_t)p * CC + cbase + tx] = tile[tx][ty + j * 8];
        }
    } else {
        int z = (bid - T_TILES) * 256 + tid;    // 0 .. NPIX/4-1
        ((int4*)d_count)[z] = make_int4(0, 0, 0, 0);
    }
}

// ------------------------------------------------- build candidate lists
// r = 3/1216 NDC. Row pitch 2/352 > 2r -> only row i0 qualifies.
// Col pitch 2/1216, 2r spans <=3 centers -> only j0-1..j0+1.
__global__ void __launch_bounds__(256)
build_kernel(const float* __restrict__ pts) {
    int t = blockIdx.x * blockDim.x + threadIdx.x;
    if (t >= BB * PP) return;
    int b = t >> 16;

    float x = pts[3 * t + 0];
    float y = pts[3 * t + 1];
    float z = pts[3 * t + 2];

    const float r2     = (3.0f / 1216.0f) * (3.0f / 1216.0f);
    const float inv_r2 = 1216.0f * 1216.0f / 9.0f;

    int i0 = (int)floorf((y + 1.0f) * 0.5f * (float)HH);
    int j0 = (int)floorf((x + 1.0f) * 0.5f * (float)WW);

    if (!(z > 0.0f) || i0 < 0 || i0 >= HH) return;

    float yc  = ((float)i0 + 0.5f) * (2.0f / (float)HH) - 1.0f;
    float fy2 = (y - yc) * (y - yc);

    #pragma unroll
    for (int dxi = -1; dxi <= 1; dxi++) {
        int jj = j0 + dxi;
        if (jj < 0 || jj >= WW) continue;
        float xc = ((float)jj + 0.5f) * (2.0f / (float)WW) - 1.0f;
        float fx = x - xc;
        float d2 = fx * fx + fy2;
        if (d2 < r2) {
            float alpha = 1.0f - sqrtf(fmaxf(d2 * inv_r2, 0.001f));
            int pix = (b * HH + i0) * WW + jj;
            int idx = atomicAdd(&d_count[pix], 1);
            if (idx < MAXC)
                d_cand[pix * MAXC + idx] = make_uint2((unsigned)t, __float_as_uint(alpha));
        }
    }
}

// ------------------------------------------------- gather
// Thread = one pixel x 8 channels (proven R3 form), now capped at 32 regs
// so 8 blocks/SM = 2048 threads/SM (100% occupancy cap).
__global__ void __launch_bounds__(256, 8)
gather_kernel(float* __restrict__ out) {
    int pix = blockIdx.x * 256 + threadIdx.x;
    int g   = blockIdx.y;

    int n = d_count[pix];
    n = n < MAXC ? n : MAXC;

    float acc[8] = {0.f, 0.f, 0.f, 0.f, 0.f, 0.f, 0.f, 0.f};
    const uint2* cbase = d_cand + pix * MAXC;
    for (int i = 0; i < n; i++) {
        uint2 e = cbase[i];
        float w = __uint_as_float(e.y);
        const float4* fp = (const float4*)(d_featsT + (size_t)e.x * CC + g * 8);
        float4 a = fp[0];
        float4 c = fp[1];
        acc[0] += w * a.x; acc[1] += w * a.y; acc[2] += w * a.z; acc[3] += w * a.w;
        acc[4] += w * c.x; acc[5] += w * c.y; acc[6] += w * c.z; acc[7] += w * c.w;
    }

    int b   = pix / HW;
    int loc = pix - b * HW;
    float* ob = out + (size_t)b * CC * HW + (size_t)(g * 8) * HW + loc;
    #pragma unroll
    for (int c = 0; c < 8; c++)
        ob[(size_t)c * HW] = acc[c];
}

extern "C" void kernel_launch(void* const* d_in, const int* in_sizes, int n_in,
                              void* d_out, int out_size) {
    const float* pts = (const float*)d_in[0];   // [B, P, 3]
    const float* src = (const float*)d_in[1];   // [B, C, P]
    float* out = (float*)d_out;                 // [B, C, H, W]

    prep_kernel<<<T_TILES + Z_BLOCKS, 256>>>(src);
    build_kernel<<<(BB * PP) / 256, 256>>>(pts);

    dim3 ggrid(NPIX / 256, 8);                  // (3344, 8)
    gather_kernel<<<ggrid, 256>>>(out);
}